// round 13
// baseline (speedup 1.0000x reference)
#include <cuda_runtime.h>
#include <cuda_fp16.h>
#include <cstdint>

#define Bb 16
#define Ll 2048
#define Ee 1024
#define Dk 128
#define Mtot (Bb*Ll)   // 32768

// Single fp16 planes: Q (qscale folded), K, V.
__device__ __half g_Qf[Mtot*Dk];
__device__ __half g_Kf[Mtot*Dk];
__device__ __half g_Vf[Mtot*Dk];
// Weights: [mat(3)][N=128][K=1024] fp16, pre-scaled by 32 (epilogue /32).
__device__ __half g_Wt[3 * 128 * 1024];

#define QSCALE 0.12751743f   /* log2(e)/sqrt(128) */

__device__ __forceinline__ uint32_t smem_u32(const void* p) {
    uint32_t a;
    asm("{ .reg .u64 t; cvta.to.shared.u64 t, %1; cvt.u32.u64 %0, t; }"
        : "=r"(a) : "l"(p));
    return a;
}

#define LDMX4(r, addr) \
    asm volatile("ldmatrix.sync.aligned.m8n8.x4.shared.b16 {%0,%1,%2,%3}, [%4];" \
        : "=r"((r)[0]), "=r"((r)[1]), "=r"((r)[2]), "=r"((r)[3]) : "r"(addr))

#define LDMX4T(r, addr) \
    asm volatile("ldmatrix.sync.aligned.m8n8.x4.trans.shared.b16 {%0,%1,%2,%3}, [%4];" \
        : "=r"((r)[0]), "=r"((r)[1]), "=r"((r)[2]), "=r"((r)[3]) : "r"(addr))

#define MMAF16(d, a, b0, b1) \
    asm volatile("mma.sync.aligned.m16n8k16.row.col.f32.f16.f16.f32 " \
        "{%0,%1,%2,%3}, {%4,%5,%6,%7}, {%8,%9}, {%0,%1,%2,%3};" \
        : "+f"((d)[0]), "+f"((d)[1]), "+f"((d)[2]), "+f"((d)[3]) \
        : "r"((a)[0]), "r"((a)[1]), "r"((a)[2]), "r"((a)[3]), "r"(b0), "r"(b1))

#define CP_COMMIT asm volatile("cp.async.commit_group;")
#define CP_WAIT(N) asm volatile("cp.async.wait_group %0;" :: "n"(N))

__device__ __forceinline__ void cpa16(uint32_t dst, const void* src) {
    asm volatile("cp.async.cg.shared.global [%0], [%1], 16;"
                 :: "r"(dst), "l"(src));
}

__device__ __forceinline__ uint32_t pack_h2(float x, float y) {
    __half2 h = __floats2half2_rn(x, y);
    return *(uint32_t*)&h;
}

#define APITCH 160   /* fp32 A stage pitch (bytes) */

// Cooperative fp32->fp16 stage conversion: N32 32-float segments of 8 elems.
// Each call converts segments [tid, tid+step, ...]; dest pitch 80B.
__device__ __forceinline__ void conv_seg(const char* smA, char* a16, int f) {
    int row = f >> 2, seg = f & 3;
    const char* src = smA + row * APITCH + seg * 32;
    float4 v0 = *(const float4*)(src);
    float4 v1 = *(const float4*)(src + 16);
    uint4 hv;
    hv.x = pack_h2(v0.x, v0.y);
    hv.y = pack_h2(v0.z, v0.w);
    hv.z = pack_h2(v1.x, v1.y);
    hv.w = pack_h2(v1.z, v1.w);
    *(uint4*)(a16 + row * 80 + seg * 16) = hv;
}

// ---------------------------------------------------------------------------
// Weight prep: W[1024,128] fp32 -> 32*W fp16, transposed [n][k].
// ---------------------------------------------------------------------------
__global__ void prep_weights(const float* __restrict__ Wq,
                             const float* __restrict__ Wk,
                             const float* __restrict__ Wv)
{
    __shared__ float t[32][33];
    const int mat = blockIdx.z;
    const float* W = (mat == 0) ? Wq : (mat == 1) ? Wk : Wv;
    const int k0 = blockIdx.x * 32, n0 = blockIdx.y * 32;
    const int tx = threadIdx.x, ty = threadIdx.y;
    t[ty][tx] = W[(size_t)(k0 + ty) * Dk + n0 + tx];
    __syncthreads();
    g_Wt[(size_t)mat * 131072 + (size_t)(n0 + ty) * Ee + k0 + tx] =
        __float2half_rn(t[tx][ty] * 32.0f);
}

// ---------------------------------------------------------------------------
// Fused Q+K projection: cp.async 3-stage fp32 A + W; shared A fp16 buffer
// converted ONCE per chunk (amortized over 4 warp-columns), then LDSM.
// 512 threads, 16 warps (4x4), warp tile 32x64.
// smem: 3 x (A32 20480 + W 20480) + A16 10240 = 133120 B.
// ---------------------------------------------------------------------------
#define PQK_STG 40960
#define PQK_A16 (3 * PQK_STG)
#define PROJQK_SMEM (PQK_A16 + 10240)

__global__ __launch_bounds__(512, 1) void proj_qk(
    const float* __restrict__ ctx, const int* __restrict__ lens)
{
    extern __shared__ char smraw[];
    const int tid  = threadIdx.x;
    const int lane = tid & 31;
    const int wid  = tid >> 5;
    const int wm   = wid >> 2;
    const int wn   = wid & 3;
    const int m0   = blockIdx.x * 128;

    const uint32_t sbase = smem_u32(smraw);
    const uint32_t a16b  = sbase + PQK_A16;
    char* a16 = smraw + PQK_A16;

    float acc[2][8][4];
    #pragma unroll
    for (int mt = 0; mt < 2; mt++)
        #pragma unroll
        for (int nt = 0; nt < 8; nt++)
            #pragma unroll
            for (int j = 0; j < 4; j++) acc[mt][nt][j] = 0.0f;

    const uint32_t a_row  = (uint32_t)(lane & 15);
    const uint32_t a_col2 = (uint32_t)(lane >> 4) * 16;
    const uint32_t b_row  = (uint32_t)((lane & 7) + ((lane >> 4) << 3));
    const uint32_t b_col2 = (uint32_t)((lane >> 3) & 1) * 16;

    auto copy_stage = [&](int stage, int k0) {
        const uint32_t st = sbase + stage * PQK_STG;
        #pragma unroll
        for (int i = 0; i < 2; i++) {
            int f = tid + i * 512;
            int row = f >> 3, c = f & 7;
            cpa16(st + row * APITCH + c * 16,
                  ctx + (size_t)(m0 + row) * Ee + k0 + c * 4);
        }
        #pragma unroll
        for (int i = 0; i < 2; i++) {
            int f = tid + i * 512;
            int row = f >> 2, q = f & 3;
            const __half* src = (row < 128)
                ? (g_Wt + (size_t)row * Ee)
                : (g_Wt + 131072 + (size_t)(row - 128) * Ee);
            cpa16(st + 20480 + row * 80 + q * 16, src + k0 + q * 8);
        }
    };

    auto do_mma = [&](int stage) {
        const uint32_t stW = sbase + stage * PQK_STG + 20480;
        #pragma unroll
        for (int ks = 0; ks < 2; ks++) {
            uint32_t af[2][4];
            #pragma unroll
            for (int mt = 0; mt < 2; mt++)
                LDMX4(af[mt], a16b + (wm * 32 + mt * 16 + a_row) * 80
                              + ks * 32 + a_col2);
            #pragma unroll
            for (int p = 0; p < 4; p++) {
                uint32_t nr = wn * 64 + p * 16 + b_row;
                uint32_t bh[4];
                LDMX4(bh, stW + nr * 80 + ks * 32 + b_col2);
                #pragma unroll
                for (int mt = 0; mt < 2; mt++) {
                    MMAF16(acc[mt][2*p],     af[mt], bh[0], bh[1]);
                    MMAF16(acc[mt][2*p + 1], af[mt], bh[2], bh[3]);
                }
            }
        }
    };

    copy_stage(0, 0);  CP_COMMIT;
    copy_stage(1, 32); CP_COMMIT;
    int stg = 0;
    for (int c = 0; c < 32; c++) {
        if (c < 30) { CP_WAIT(1); } else { CP_WAIT(0); }
        __syncthreads();
        if (c + 2 < 32) {
            copy_stage((stg + 2) % 3, (c + 2) * 32);
            CP_COMMIT;
        }
        conv_seg(smraw + stg * PQK_STG, a16, tid);   // 512 thr x 8 elems
        __syncthreads();
        do_mma(stg);
        stg = (stg + 1) % 3;
    }

    const int lenb = lens[m0 >> 11];
    const bool isQ = (wn < 2);
    __half* C = isQ ? g_Qf : g_Kf;
    const int ncc = isQ ? wn * 64 : (wn - 2) * 64;
    const float sc = isQ ? (QSCALE / 32.0f) : (1.0f / 32.0f);
    #pragma unroll
    for (int mt = 0; mt < 2; mt++) {
        int r = m0 + wm * 32 + mt * 16 + (lane >> 2);
        float mk0 = ((((r)     & 2047) < lenb) ? 1.0f : 0.0f) * sc;
        float mk1 = ((((r + 8) & 2047) < lenb) ? 1.0f : 0.0f) * sc;
        #pragma unroll
        for (int nt = 0; nt < 8; nt++) {
            int cc = ncc + nt * 8 + (lane & 3) * 2;
            *(uint32_t*)(C + (size_t)r * Dk + cc) =
                pack_h2(acc[mt][nt][0] * mk0, acc[mt][nt][1] * mk0);
            *(uint32_t*)(C + (size_t)(r + 8) * Dk + cc) =
                pack_h2(acc[mt][nt][2] * mk1, acc[mt][nt][3] * mk1);
        }
    }
}

// ---------------------------------------------------------------------------
// V projection: same scheme, 256 threads, 8 warps (4x2).
// smem: 3 x (20480 + 10240) + 10240 = 102400 B; 2 CTAs/SM.
// ---------------------------------------------------------------------------
#define PV_STG 30720
#define PV_A16 (3 * PV_STG)
#define PROJV_SMEM (PV_A16 + 10240)

__global__ __launch_bounds__(256, 2) void proj_v(
    const float* __restrict__ x, const int* __restrict__ lens)
{
    extern __shared__ char smraw[];
    const int tid  = threadIdx.x;
    const int lane = tid & 31;
    const int wid  = tid >> 5;
    const int wm   = wid >> 1;
    const int wn   = wid & 1;
    const int m0   = blockIdx.x * 128;
    const __half* W = g_Wt + 2 * 131072;

    const uint32_t sbase = smem_u32(smraw);
    const uint32_t a16b  = sbase + PV_A16;
    char* a16 = smraw + PV_A16;

    float acc[2][8][4];
    #pragma unroll
    for (int mt = 0; mt < 2; mt++)
        #pragma unroll
        for (int nt = 0; nt < 8; nt++)
            #pragma unroll
            for (int j = 0; j < 4; j++) acc[mt][nt][j] = 0.0f;

    const uint32_t a_row  = (uint32_t)(lane & 15);
    const uint32_t a_col2 = (uint32_t)(lane >> 4) * 16;
    const uint32_t b_row  = (uint32_t)((lane & 7) + ((lane >> 4) << 3));
    const uint32_t b_col2 = (uint32_t)((lane >> 3) & 1) * 16;

    auto copy_stage = [&](int stage, int k0) {
        const uint32_t st = sbase + stage * PV_STG;
        #pragma unroll
        for (int i = 0; i < 4; i++) {
            int f = tid + i * 256;
            int row = f >> 3, c = f & 7;
            cpa16(st + row * APITCH + c * 16,
                  x + (size_t)(m0 + row) * Ee + k0 + c * 4);
        }
        #pragma unroll
        for (int i = 0; i < 2; i++) {
            int f = tid + i * 256;
            int row = f >> 2, q = f & 3;
            cpa16(st + 20480 + row * 80 + q * 16,
                  W + (size_t)row * Ee + k0 + q * 8);
        }
    };

    auto do_mma = [&](int stage) {
        const uint32_t stW = sbase + stage * PV_STG + 20480;
        #pragma unroll
        for (int ks = 0; ks < 2; ks++) {
            uint32_t af[2][4];
            #pragma unroll
            for (int mt = 0; mt < 2; mt++)
                LDMX4(af[mt], a16b + (wm * 32 + mt * 16 + a_row) * 80
                              + ks * 32 + a_col2);
            #pragma unroll
            for (int p = 0; p < 4; p++) {
                uint32_t nr = wn * 64 + p * 16 + b_row;
                uint32_t bh[4];
                LDMX4(bh, stW + nr * 80 + ks * 32 + b_col2);
                #pragma unroll
                for (int mt = 0; mt < 2; mt++) {
                    MMAF16(acc[mt][2*p],     af[mt], bh[0], bh[1]);
                    MMAF16(acc[mt][2*p + 1], af[mt], bh[2], bh[3]);
                }
            }
        }
    };

    copy_stage(0, 0);  CP_COMMIT;
    copy_stage(1, 32); CP_COMMIT;
    int stg = 0;
    for (int c = 0; c < 32; c++) {
        if (c < 30) { CP_WAIT(1); } else { CP_WAIT(0); }
        __syncthreads();
        if (c + 2 < 32) {
            copy_stage((stg + 2) % 3, (c + 2) * 32);
            CP_COMMIT;
        }
        #pragma unroll
        for (int i = 0; i < 2; i++)
            conv_seg(smraw + stg * PV_STG, a16, tid + i * 256);
        __syncthreads();
        do_mma(stg);
        stg = (stg + 1) % 3;
    }

    const int lenb = lens[m0 >> 11];
    const float sc = 1.0f / 32.0f;
    #pragma unroll
    for (int mt = 0; mt < 2; mt++) {
        int r = m0 + wm * 32 + mt * 16 + (lane >> 2);
        float mk0 = ((((r)     & 2047) < lenb) ? 1.0f : 0.0f) * sc;
        float mk1 = ((((r + 8) & 2047) < lenb) ? 1.0f : 0.0f) * sc;
        #pragma unroll
        for (int nt = 0; nt < 8; nt++) {
            int cc = wn * 64 + nt * 8 + (lane & 3) * 2;
            *(uint32_t*)(g_Vf + (size_t)r * Dk + cc) =
                pack_h2(acc[mt][nt][0] * mk0, acc[mt][nt][1] * mk0);
            *(uint32_t*)(g_Vf + (size_t)(r + 8) * Dk + cc) =
                pack_h2(acc[mt][nt][2] * mk1, acc[mt][nt][3] * mk1);
        }
    }
}

// ---------------------------------------------------------------------------
// Flash attention: BQ=64, BK=64, 128 threads, now 3 CTAs/SM (reg cap 170).
// Register-P, conditional rescale, diagonal-only masking, LPT.
// smem: Q 17408 | K 2x17408 | V 17408 = 69632 B (3x = 208896 <= 227KB).
// ---------------------------------------------------------------------------
#define AQP 272
#define SM_Qf 0
#define SM_K  17408
#define SM_V  52224
#define ATTN_SMEM 69632

__global__ __launch_bounds__(128, 3) void attn_mma(
    float* __restrict__ Out, const int* __restrict__ lens)
{
    extern __shared__ char sm[];
    const uint32_t sb = smem_u32(sm);
    const int tid  = threadIdx.x;
    const int lane = tid & 31;
    const int warp = tid >> 5;
    const int b    = blockIdx.x;
    const int q0   = (gridDim.y - 1 - blockIdx.y) * 64;
    const int len  = lens[b];

    const uint32_t a_row = lane & 15;
    const uint32_t a_col = (uint32_t)(lane >> 4) * 16;
    const uint32_t b_row = (lane & 7) + ((lane >> 4) << 3);
    const uint32_t b_col = (uint32_t)((lane >> 3) & 1) * 16;
    const uint32_t v_k   = (lane & 7) + ((lane >> 3) & 1) * 8;
    const uint32_t v_d   = (uint32_t)(lane >> 4) * 16;

    auto copy_Q = [&]() {
        #pragma unroll
        for (int i = 0; i < 8; i++) {
            int f = tid + i * 128;
            int row = f >> 4, c = f & 15;
            cpa16(sb + SM_Qf + row * AQP + c * 16,
                  g_Qf + (size_t)(b * Ll + q0 + row) * Dk + c * 8);
        }
    };
    auto copy_K = [&](int stage, int j0) {
        const uint32_t kb = sb + SM_K + stage * 17408;
        #pragma unroll
        for (int i = 0; i < 8; i++) {
            int f = tid + i * 128;
            int row = f >> 4, c = f & 15;
            cpa16(kb + row * AQP + c * 16,
                  g_Kf + (size_t)(b * Ll + j0 + row) * Dk + c * 8);
        }
    };
    auto copy_V = [&](int j0) {
        #pragma unroll
        for (int i = 0; i < 8; i++) {
            int f = tid + i * 128;
            int row = f >> 4, c = f & 15;
            cpa16(sb + SM_V + row * AQP + c * 16,
                  g_Vf + (size_t)(b * Ll + j0 + row) * Dk + c * 8);
        }
    };

    float o[16][4];
    #pragma unroll
    for (int nt = 0; nt < 16; nt++)
        #pragma unroll
        for (int j = 0; j < 4; j++) o[nt][j] = 0.0f;
    float mrow[2] = {-1e30f, -1e30f};
    float lrow[2] = {0.0f, 0.0f};

    const int kend = min(len, q0 + 64);

    copy_Q();
    copy_K(0, 0);
    CP_COMMIT;
    CP_WAIT(0);
    __syncthreads();

    int cur = 0;
    for (int j0 = 0; j0 < kend; j0 += 64) {
        copy_V(j0);
        CP_COMMIT;

        float s[8][4];
        #pragma unroll
        for (int t = 0; t < 8; t++)
            #pragma unroll
            for (int j = 0; j < 4; j++) s[t][j] = 0.0f;

        const uint32_t kbase = sb + SM_K + cur * 17408;
        #pragma unroll
        for (int ks = 0; ks < 8; ks++) {
            uint32_t qf[4];
            LDMX4(qf, sb + SM_Qf + (warp * 16 + a_row) * AQP + ks * 32 + a_col);
            #pragma unroll
            for (int p = 0; p < 4; p++) {
                uint32_t bh[4];
                LDMX4(bh, kbase + (p * 16 + b_row) * AQP + ks * 32 + b_col);
                MMAF16(s[2*p],     qf, bh[0], bh[1]);
                MMAF16(s[2*p + 1], qf, bh[2], bh[3]);
            }
        }

        bool more = (j0 + 64 < kend);
        if (more) {
            copy_K(cur ^ 1, j0 + 64);
            CP_COMMIT;
            CP_WAIT(1);
        } else {
            CP_WAIT(0);
        }
        __syncthreads();

        const bool nomask = (j0 + 64 <= q0 + warp * 16 + 1) && (j0 + 64 <= len);

        #pragma unroll
        for (int h = 0; h < 2; h++) {
            const int qi = q0 + warp * 16 + (lane >> 2) + h * 8;
            float mx = -1e30f;
            if (nomask) {
                #pragma unroll
                for (int t = 0; t < 8; t++)
                    mx = fmaxf(mx, fmaxf(s[t][2*h], s[t][2*h + 1]));
            } else {
                #pragma unroll
                for (int t = 0; t < 8; t++) {
                    int c = j0 + t * 8 + (lane & 3) * 2;
                    float v0 = (c     <= qi && c     < len) ? s[t][2*h]     : -1e30f;
                    float v1 = (c + 1 <= qi && c + 1 < len) ? s[t][2*h + 1] : -1e30f;
                    s[t][2*h] = v0; s[t][2*h + 1] = v1;
                    mx = fmaxf(mx, fmaxf(v0, v1));
                }
            }
            mx = fmaxf(mx, __shfl_xor_sync(0xffffffffu, mx, 1));
            mx = fmaxf(mx, __shfl_xor_sync(0xffffffffu, mx, 2));
            float mnew = fmaxf(mrow[h], mx);
            float lsum = 0.0f;
            #pragma unroll
            for (int t = 0; t < 8; t++) {
                float p0 = exp2f(s[t][2*h]     - mnew);
                float p1 = exp2f(s[t][2*h + 1] - mnew);
                lsum += p0 + p1;
                s[t][2*h] = __uint_as_float(pack_h2(p0, p1));
            }
            lsum += __shfl_xor_sync(0xffffffffu, lsum, 1);
            lsum += __shfl_xor_sync(0xffffffffu, lsum, 2);
            if (mnew > mrow[h]) {
                float alpha = exp2f(mrow[h] - mnew);
                lrow[h] = lrow[h] * alpha + lsum;
                mrow[h] = mnew;
                #pragma unroll
                for (int nt = 0; nt < 16; nt++) {
                    o[nt][2*h]     *= alpha;
                    o[nt][2*h + 1] *= alpha;
                }
            } else {
                lrow[h] += lsum;
            }
        }

        #pragma unroll
        for (int ks = 0; ks < 4; ks++) {
            uint32_t pa[4];
            pa[0] = __float_as_uint(s[2*ks][0]);
            pa[1] = __float_as_uint(s[2*ks][2]);
            pa[2] = __float_as_uint(s[2*ks + 1][0]);
            pa[3] = __float_as_uint(s[2*ks + 1][2]);
            #pragma unroll
            for (int dt = 0; dt < 8; dt++) {
                uint32_t bh[4];
                LDMX4T(bh, sb + SM_V + (ks * 16 + v_k) * AQP + dt * 32 + v_d);
                MMAF16(o[2*dt],     pa, bh[0], bh[1]);
                MMAF16(o[2*dt + 1], pa, bh[2], bh[3]);
            }
        }
        CP_WAIT(0);
        __syncthreads();
        cur ^= 1;
    }

    #pragma unroll
    for (int h = 0; h < 2; h++) {
        float inv = 1.0f / lrow[h];
        int row = q0 + warp * 16 + (lane >> 2) + h * 8;
        float* og = Out + ((size_t)(b * Ll + row)) * Dk;
        #pragma unroll
        for (int dt = 0; dt < 16; dt++) {
            float2 v;
            v.x = o[dt][2*h]     * inv;
            v.y = o[dt][2*h + 1] * inv;
            *(float2*)(og + dt * 8 + (lane & 3) * 2) = v;
        }
    }
}

// ---------------------------------------------------------------------------
extern "C" void kernel_launch(void* const* d_in, const int* in_sizes, int n_in,
                              void* d_out, int out_size)
{
    const float* x    = (const float*)d_in[0];
    const float* ctx  = (const float*)d_in[1];
    const int*   lens = (const int*)  d_in[2];
    const float* Wq   = (const float*)d_in[3];
    const float* Wk   = (const float*)d_in[4];
    const float* Wv   = (const float*)d_in[5];
    float* out = (float*)d_out;
    (void)in_sizes; (void)n_in; (void)out_size;

    prep_weights<<<dim3(32, 4, 3), dim3(32, 32)>>>(Wq, Wk, Wv);

    cudaFuncSetAttribute(proj_qk,
                         cudaFuncAttributeMaxDynamicSharedMemorySize, PROJQK_SMEM);
    proj_qk<<<Mtot / 128, 512, PROJQK_SMEM>>>(ctx, lens);

    cudaFuncSetAttribute(proj_v,
                         cudaFuncAttributeMaxDynamicSharedMemorySize, PROJV_SMEM);
    proj_v<<<Mtot / 128, 256, PROJV_SMEM>>>(x, lens);

    cudaFuncSetAttribute(attn_mma,
                         cudaFuncAttributeMaxDynamicSharedMemorySize, ATTN_SMEM);
    attn_mma<<<dim3(Bb, Ll / 64), 128, ATTN_SMEM>>>(out, lens);
}

// round 14
// speedup vs baseline: 1.0544x; 1.0544x over previous
#include <cuda_runtime.h>
#include <cuda_fp16.h>
#include <cstdint>

#define Bb 16
#define Ll 2048
#define Ee 1024
#define Dk 128
#define Mtot (Bb*Ll)   // 32768

__device__ __half g_Qf[Mtot*Dk];
__device__ __half g_Kf[Mtot*Dk];
__device__ __half g_Vf[Mtot*Dk];
// Weights: [mat(3)][N=128][K=1024] fp16, pre-scaled by 32 (epilogue /32).
__device__ __half g_Wt[3 * 128 * 1024];

#define QSCALE 0.12751743f   /* log2(e)/sqrt(128) */

__device__ __forceinline__ uint32_t smem_u32(const void* p) {
    uint32_t a;
    asm("{ .reg .u64 t; cvta.to.shared.u64 t, %1; cvt.u32.u64 %0, t; }"
        : "=r"(a) : "l"(p));
    return a;
}

#define LDMX4(r, addr) \
    asm volatile("ldmatrix.sync.aligned.m8n8.x4.shared.b16 {%0,%1,%2,%3}, [%4];" \
        : "=r"((r)[0]), "=r"((r)[1]), "=r"((r)[2]), "=r"((r)[3]) : "r"(addr))

#define LDMX4T(r, addr) \
    asm volatile("ldmatrix.sync.aligned.m8n8.x4.trans.shared.b16 {%0,%1,%2,%3}, [%4];" \
        : "=r"((r)[0]), "=r"((r)[1]), "=r"((r)[2]), "=r"((r)[3]) : "r"(addr))

#define MMAF16(d, a, b0, b1) \
    asm volatile("mma.sync.aligned.m16n8k16.row.col.f32.f16.f16.f32 " \
        "{%0,%1,%2,%3}, {%4,%5,%6,%7}, {%8,%9}, {%0,%1,%2,%3};" \
        : "+f"((d)[0]), "+f"((d)[1]), "+f"((d)[2]), "+f"((d)[3]) \
        : "r"((a)[0]), "r"((a)[1]), "r"((a)[2]), "r"((a)[3]), "r"(b0), "r"(b1))

#define CP_COMMIT asm volatile("cp.async.commit_group;")
#define CP_WAIT(N) asm volatile("cp.async.wait_group %0;" :: "n"(N))

__device__ __forceinline__ void cpa16(uint32_t dst, const void* src) {
    asm volatile("cp.async.cg.shared.global [%0], [%1], 16;"
                 :: "r"(dst), "l"(src));
}

__device__ __forceinline__ uint32_t pack_h2(float x, float y) {
    __half2 h = __floats2half2_rn(x, y);
    return *(uint32_t*)&h;
}

// Assemble one m16n8k16 A-fragment (4 regs) from fp32 smem (pitch APITCH).
#define APITCH 160
__device__ __forceinline__ void a_frag_f32(uint32_t* a, const char* smA,
                                           int rb, int cb, int lane) {
    int r  = rb + (lane >> 2);
    int c  = cb + (lane & 3) * 2;
    float2 v0 = *(const float2*)(smA + r * APITCH + c * 4);
    float2 v1 = *(const float2*)(smA + (r + 8) * APITCH + c * 4);
    float2 v2 = *(const float2*)(smA + r * APITCH + (c + 8) * 4);
    float2 v3 = *(const float2*)(smA + (r + 8) * APITCH + (c + 8) * 4);
    a[0] = pack_h2(v0.x, v0.y);
    a[1] = pack_h2(v1.x, v1.y);
    a[2] = pack_h2(v2.x, v2.y);
    a[3] = pack_h2(v3.x, v3.y);
}

// ---------------------------------------------------------------------------
// Weight prep: W[1024,128] fp32 -> 32*W fp16, transposed [n][k].
// ---------------------------------------------------------------------------
__global__ void prep_weights(const float* __restrict__ Wq,
                             const float* __restrict__ Wk,
                             const float* __restrict__ Wv)
{
    __shared__ float t[32][33];
    const int mat = blockIdx.z;
    const float* W = (mat == 0) ? Wq : (mat == 1) ? Wk : Wv;
    const int k0 = blockIdx.x * 32, n0 = blockIdx.y * 32;
    const int tx = threadIdx.x, ty = threadIdx.y;
    t[ty][tx] = W[(size_t)(k0 + ty) * Dk + n0 + tx];
    __syncthreads();
    g_Wt[(size_t)mat * 131072 + (size_t)(n0 + ty) * Ee + k0 + tx] =
        __float2half_rn(t[tx][ty] * 32.0f);
}

// ---------------------------------------------------------------------------
// Merged projection, 512 CTAs x 512 threads, single launch (wave-packed):
//   bid <  256 : QK tile — C[128,256] = ctx_tile @ [Wq|Wk], warp 32x64 (R12).
//   bid >= 256 : V  tile — C[128,128] = x_tile @ Wv, 16 warps, warp 32x32.
// cp.async 3-stage; A fp32 in smem; W fp16. Heavy QK CTAs launch first.
// ---------------------------------------------------------------------------
#define PQK_STG 40960
#define PROJ_SMEM (3 * PQK_STG)

__global__ __launch_bounds__(512, 1) void proj_all(
    const float* __restrict__ x, const float* __restrict__ ctx,
    const int* __restrict__ lens)
{
    extern __shared__ char smraw[];
    const int tid  = threadIdx.x;
    const int lane = tid & 31;
    const int wid  = tid >> 5;
    const int wm   = wid >> 2;      // 0..3 -> 32-row band
    const int wn   = wid & 3;       // 0..3
    const bool isV = (blockIdx.x >= 256);
    const int m0   = (isV ? blockIdx.x - 256 : blockIdx.x) * 128;
    const float* A = isV ? x : ctx;

    const uint32_t sbase = smem_u32(smraw);

    float acc[2][8][4];
    #pragma unroll
    for (int mt = 0; mt < 2; mt++)
        #pragma unroll
        for (int nt = 0; nt < 8; nt++)
            #pragma unroll
            for (int j = 0; j < 4; j++) acc[mt][nt][j] = 0.0f;

    const uint32_t b_row  = (uint32_t)((lane & 7) + ((lane >> 4) << 3));
    const uint32_t b_col2 = (uint32_t)((lane >> 3) & 1) * 16;

    auto copy_stage = [&](int stage, int k0) {
        const uint32_t st = sbase + stage * PQK_STG;
        // A: 128 rows x 128B fp32 -> 1024 cpa16, 2/thread
        #pragma unroll
        for (int i = 0; i < 2; i++) {
            int f = tid + i * 512;
            int row = f >> 3, c = f & 7;
            cpa16(st + row * APITCH + c * 16,
                  A + (size_t)(m0 + row) * Ee + k0 + c * 4);
        }
        if (isV) {
            // W: 128 rows x 64B -> 512 cpa16, 1/thread
            int row = tid >> 2, q = tid & 3;
            cpa16(st + 20480 + row * 80 + q * 16,
                  g_Wt + 2 * 131072 + (size_t)row * Ee + k0 + q * 8);
        } else {
            // W: 256 rows x 64B -> 1024 cpa16, 2/thread
            #pragma unroll
            for (int i = 0; i < 2; i++) {
                int f = tid + i * 512;
                int row = f >> 2, q = f & 3;
                const __half* src = (row < 128)
                    ? (g_Wt + (size_t)row * Ee)
                    : (g_Wt + 131072 + (size_t)(row - 128) * Ee);
                cpa16(st + 20480 + row * 80 + q * 16, src + k0 + q * 8);
            }
        }
    };

    auto do_mma = [&](int stage) {
        const char* smA = smraw + stage * PQK_STG;
        const uint32_t stW = sbase + stage * PQK_STG + 20480;
        #pragma unroll
        for (int ks = 0; ks < 2; ks++) {
            uint32_t af[2][4];
            #pragma unroll
            for (int mt = 0; mt < 2; mt++)
                a_frag_f32(af[mt], smA, wm * 32 + mt * 16, ks * 16, lane);
            if (isV) {
                #pragma unroll
                for (int p = 0; p < 2; p++) {
                    uint32_t nr = wn * 32 + p * 16 + b_row;
                    uint32_t bh[4];
                    LDMX4(bh, stW + nr * 80 + ks * 32 + b_col2);
                    #pragma unroll
                    for (int mt = 0; mt < 2; mt++) {
                        MMAF16(acc[mt][2*p],     af[mt], bh[0], bh[1]);
                        MMAF16(acc[mt][2*p + 1], af[mt], bh[2], bh[3]);
                    }
                }
            } else {
                #pragma unroll
                for (int p = 0; p < 4; p++) {
                    uint32_t nr = wn * 64 + p * 16 + b_row;
                    uint32_t bh[4];
                    LDMX4(bh, stW + nr * 80 + ks * 32 + b_col2);
                    #pragma unroll
                    for (int mt = 0; mt < 2; mt++) {
                        MMAF16(acc[mt][2*p],     af[mt], bh[0], bh[1]);
                        MMAF16(acc[mt][2*p + 1], af[mt], bh[2], bh[3]);
                    }
                }
            }
        }
    };

    copy_stage(0, 0);  CP_COMMIT;
    copy_stage(1, 32); CP_COMMIT;
    int stg = 0;
    for (int c = 0; c < 32; c++) {
        if (c < 30) { CP_WAIT(1); } else { CP_WAIT(0); }
        __syncthreads();
        if (c + 2 < 32) {
            copy_stage((stg + 2) % 3, (c + 2) * 32);
            CP_COMMIT;
        }
        do_mma(stg);
        stg = (stg + 1) % 3;
    }

    // Epilogue
    const int lenb = lens[m0 >> 11];
    __half* C;
    int ncc, nts;
    float sc;
    if (isV)         { C = g_Vf; ncc = wn * 32;       nts = 4; sc = 1.0f / 32.0f; }
    else if (wn < 2) { C = g_Qf; ncc = wn * 64;       nts = 8; sc = QSCALE / 32.0f; }
    else             { C = g_Kf; ncc = (wn - 2) * 64; nts = 8; sc = 1.0f / 32.0f; }
    #pragma unroll
    for (int mt = 0; mt < 2; mt++) {
        int r = m0 + wm * 32 + mt * 16 + (lane >> 2);
        float mk0 = ((((r)     & 2047) < lenb) ? 1.0f : 0.0f) * sc;
        float mk1 = ((((r + 8) & 2047) < lenb) ? 1.0f : 0.0f) * sc;
        for (int nt = 0; nt < nts; nt++) {
            int cc = ncc + nt * 8 + (lane & 3) * 2;
            *(uint32_t*)(C + (size_t)r * Dk + cc) =
                pack_h2(acc[mt][nt][0] * mk0, acc[mt][nt][1] * mk0);
            *(uint32_t*)(C + (size_t)(r + 8) * Dk + cc) =
                pack_h2(acc[mt][nt][2] * mk1, acc[mt][nt][3] * mk1);
        }
    }
}

// ---------------------------------------------------------------------------
// Flash attention (R12-proven, 59.7us): BQ=64, BK=64, 128 threads, 2 CTAs/SM.
// Register-P, conditional rescale, diagonal-only masking, LPT.
// smem: Q 17408 | K 2x17408 | V 17408 = 69632 B.
// ---------------------------------------------------------------------------
#define AQP 272
#define SM_Qf 0
#define SM_K  17408
#define SM_V  52224
#define ATTN_SMEM 69632

__global__ __launch_bounds__(128, 2) void attn_mma(
    float* __restrict__ Out, const int* __restrict__ lens)
{
    extern __shared__ char sm[];
    const uint32_t sb = smem_u32(sm);
    const int tid  = threadIdx.x;
    const int lane = tid & 31;
    const int warp = tid >> 5;
    const int b    = blockIdx.x;
    const int q0   = (gridDim.y - 1 - blockIdx.y) * 64;
    const int len  = lens[b];

    const uint32_t a_row = lane & 15;
    const uint32_t a_col = (uint32_t)(lane >> 4) * 16;
    const uint32_t b_row = (lane & 7) + ((lane >> 4) << 3);
    const uint32_t b_col = (uint32_t)((lane >> 3) & 1) * 16;
    const uint32_t v_k   = (lane & 7) + ((lane >> 3) & 1) * 8;
    const uint32_t v_d   = (uint32_t)(lane >> 4) * 16;

    auto copy_Q = [&]() {
        #pragma unroll
        for (int i = 0; i < 8; i++) {
            int f = tid + i * 128;
            int row = f >> 4, c = f & 15;
            cpa16(sb + SM_Qf + row * AQP + c * 16,
                  g_Qf + (size_t)(b * Ll + q0 + row) * Dk + c * 8);
        }
    };
    auto copy_K = [&](int stage, int j0) {
        const uint32_t kb = sb + SM_K + stage * 17408;
        #pragma unroll
        for (int i = 0; i < 8; i++) {
            int f = tid + i * 128;
            int row = f >> 4, c = f & 15;
            cpa16(kb + row * AQP + c * 16,
                  g_Kf + (size_t)(b * Ll + j0 + row) * Dk + c * 8);
        }
    };
    auto copy_V = [&](int j0) {
        #pragma unroll
        for (int i = 0; i < 8; i++) {
            int f = tid + i * 128;
            int row = f >> 4, c = f & 15;
            cpa16(sb + SM_V + row * AQP + c * 16,
                  g_Vf + (size_t)(b * Ll + j0 + row) * Dk + c * 8);
        }
    };

    float o[16][4];
    #pragma unroll
    for (int nt = 0; nt < 16; nt++)
        #pragma unroll
        for (int j = 0; j < 4; j++) o[nt][j] = 0.0f;
    float mrow[2] = {-1e30f, -1e30f};
    float lrow[2] = {0.0f, 0.0f};

    const int kend = min(len, q0 + 64);

    copy_Q();
    copy_K(0, 0);
    CP_COMMIT;
    CP_WAIT(0);
    __syncthreads();

    int cur = 0;
    for (int j0 = 0; j0 < kend; j0 += 64) {
        copy_V(j0);
        CP_COMMIT;

        float s[8][4];
        #pragma unroll
        for (int t = 0; t < 8; t++)
            #pragma unroll
            for (int j = 0; j < 4; j++) s[t][j] = 0.0f;

        const uint32_t kbase = sb + SM_K + cur * 17408;
        #pragma unroll
        for (int ks = 0; ks < 8; ks++) {
            uint32_t qf[4];
            LDMX4(qf, sb + SM_Qf + (warp * 16 + a_row) * AQP + ks * 32 + a_col);
            #pragma unroll
            for (int p = 0; p < 4; p++) {
                uint32_t bh[4];
                LDMX4(bh, kbase + (p * 16 + b_row) * AQP + ks * 32 + b_col);
                MMAF16(s[2*p],     qf, bh[0], bh[1]);
                MMAF16(s[2*p + 1], qf, bh[2], bh[3]);
            }
        }

        bool more = (j0 + 64 < kend);
        if (more) {
            copy_K(cur ^ 1, j0 + 64);
            CP_COMMIT;
            CP_WAIT(1);
        } else {
            CP_WAIT(0);
        }
        __syncthreads();

        const bool nomask = (j0 + 64 <= q0 + warp * 16 + 1) && (j0 + 64 <= len);

        #pragma unroll
        for (int h = 0; h < 2; h++) {
            const int qi = q0 + warp * 16 + (lane >> 2) + h * 8;
            float mx = -1e30f;
            if (nomask) {
                #pragma unroll
                for (int t = 0; t < 8; t++)
                    mx = fmaxf(mx, fmaxf(s[t][2*h], s[t][2*h + 1]));
            } else {
                #pragma unroll
                for (int t = 0; t < 8; t++) {
                    int c = j0 + t * 8 + (lane & 3) * 2;
                    float v0 = (c     <= qi && c     < len) ? s[t][2*h]     : -1e30f;
                    float v1 = (c + 1 <= qi && c + 1 < len) ? s[t][2*h + 1] : -1e30f;
                    s[t][2*h] = v0; s[t][2*h + 1] = v1;
                    mx = fmaxf(mx, fmaxf(v0, v1));
                }
            }
            mx = fmaxf(mx, __shfl_xor_sync(0xffffffffu, mx, 1));
            mx = fmaxf(mx, __shfl_xor_sync(0xffffffffu, mx, 2));
            float mnew = fmaxf(mrow[h], mx);
            float lsum = 0.0f;
            #pragma unroll
            for (int t = 0; t < 8; t++) {
                float p0 = exp2f(s[t][2*h]     - mnew);
                float p1 = exp2f(s[t][2*h + 1] - mnew);
                lsum += p0 + p1;
                s[t][2*h] = __uint_as_float(pack_h2(p0, p1));
            }
            lsum += __shfl_xor_sync(0xffffffffu, lsum, 1);
            lsum += __shfl_xor_sync(0xffffffffu, lsum, 2);
            if (mnew > mrow[h]) {
                float alpha = exp2f(mrow[h] - mnew);
                lrow[h] = lrow[h] * alpha + lsum;
                mrow[h] = mnew;
                #pragma unroll
                for (int nt = 0; nt < 16; nt++) {
                    o[nt][2*h]     *= alpha;
                    o[nt][2*h + 1] *= alpha;
                }
            } else {
                lrow[h] += lsum;
            }
        }

        #pragma unroll
        for (int ks = 0; ks < 4; ks++) {
            uint32_t pa[4];
            pa[0] = __float_as_uint(s[2*ks][0]);
            pa[1] = __float_as_uint(s[2*ks][2]);
            pa[2] = __float_as_uint(s[2*ks + 1][0]);
            pa[3] = __float_as_uint(s[2*ks + 1][2]);
            #pragma unroll
            for (int dt = 0; dt < 8; dt++) {
                uint32_t bh[4];
                LDMX4T(bh, sb + SM_V + (ks * 16 + v_k) * AQP + dt * 32 + v_d);
                MMAF16(o[2*dt],     pa, bh[0], bh[1]);
                MMAF16(o[2*dt + 1], pa, bh[2], bh[3]);
            }
        }
        CP_WAIT(0);
        __syncthreads();
        cur ^= 1;
    }

    #pragma unroll
    for (int h = 0; h < 2; h++) {
        float inv = 1.0f / lrow[h];
        int row = q0 + warp * 16 + (lane >> 2) + h * 8;
        float* og = Out + ((size_t)(b * Ll + row)) * Dk;
        #pragma unroll
        for (int dt = 0; dt < 16; dt++) {
            float2 v;
            v.x = o[dt][2*h]     * inv;
            v.y = o[dt][2*h + 1] * inv;
            *(float2*)(og + dt * 8 + (lane & 3) * 2) = v;
        }
    }
}

// ---------------------------------------------------------------------------
extern "C" void kernel_launch(void* const* d_in, const int* in_sizes, int n_in,
                              void* d_out, int out_size)
{
    const float* x    = (const float*)d_in[0];
    const float* ctx  = (const float*)d_in[1];
    const int*   lens = (const int*)  d_in[2];
    const float* Wq   = (const float*)d_in[3];
    const float* Wk   = (const float*)d_in[4];
    const float* Wv   = (const float*)d_in[5];
    float* out = (float*)d_out;
    (void)in_sizes; (void)n_in; (void)out_size;

    prep_weights<<<dim3(32, 4, 3), dim3(32, 32)>>>(Wq, Wk, Wv);

    cudaFuncSetAttribute(proj_all,
                         cudaFuncAttributeMaxDynamicSharedMemorySize, PROJ_SMEM);
    proj_all<<<512, 512, PROJ_SMEM>>>(x, ctx, lens);

    cudaFuncSetAttribute(attn_mma,
                         cudaFuncAttributeMaxDynamicSharedMemorySize, ATTN_SMEM);
    attn_mma<<<dim3(Bb, Ll / 64), 128, ATTN_SMEM>>>(out, lens);
}

// round 15
// speedup vs baseline: 1.1437x; 1.0847x over previous
#include <cuda_runtime.h>
#include <cuda_fp16.h>
#include <cstdint>

#define Bb 16
#define Ll 2048
#define Ee 1024
#define Dk 128
#define Mtot (Bb*Ll)   // 32768

__device__ __half g_Qf[Mtot*Dk];
__device__ __half g_Kf[Mtot*Dk];
__device__ __half g_Vf[Mtot*Dk];
// Weights: [mat(3)][N=128][K=1024] fp16, pre-scaled by 32 (epilogue /32).
__device__ __half g_Wt[3 * 128 * 1024];

#define QSCALE 0.12751743f   /* log2(e)/sqrt(128) */

__device__ __forceinline__ uint32_t smem_u32(const void* p) {
    uint32_t a;
    asm("{ .reg .u64 t; cvta.to.shared.u64 t, %1; cvt.u32.u64 %0, t; }"
        : "=r"(a) : "l"(p));
    return a;
}

#define LDMX4(r, addr) \
    asm volatile("ldmatrix.sync.aligned.m8n8.x4.shared.b16 {%0,%1,%2,%3}, [%4];" \
        : "=r"((r)[0]), "=r"((r)[1]), "=r"((r)[2]), "=r"((r)[3]) : "r"(addr))

#define LDMX4T(r, addr) \
    asm volatile("ldmatrix.sync.aligned.m8n8.x4.trans.shared.b16 {%0,%1,%2,%3}, [%4];" \
        : "=r"((r)[0]), "=r"((r)[1]), "=r"((r)[2]), "=r"((r)[3]) : "r"(addr))

#define MMAF16(d, a, b0, b1) \
    asm volatile("mma.sync.aligned.m16n8k16.row.col.f32.f16.f16.f32 " \
        "{%0,%1,%2,%3}, {%4,%5,%6,%7}, {%8,%9}, {%0,%1,%2,%3};" \
        : "+f"((d)[0]), "+f"((d)[1]), "+f"((d)[2]), "+f"((d)[3]) \
        : "r"((a)[0]), "r"((a)[1]), "r"((a)[2]), "r"((a)[3]), "r"(b0), "r"(b1))

#define CP_COMMIT asm volatile("cp.async.commit_group;")
#define CP_WAIT(N) asm volatile("cp.async.wait_group %0;" :: "n"(N))

__device__ __forceinline__ void cpa16(uint32_t dst, const void* src) {
    asm volatile("cp.async.cg.shared.global [%0], [%1], 16;"
                 :: "r"(dst), "l"(src));
}

__device__ __forceinline__ uint32_t pack_h2(float x, float y) {
    __half2 h = __floats2half2_rn(x, y);
    return *(uint32_t*)&h;
}

// Assemble one m16n8k16 A-fragment (4 regs) from fp32 smem (given pitch).
__device__ __forceinline__ void a_frag_f32p(uint32_t* a, const char* smA,
                                            int pitch, int rb, int cb, int lane) {
    int r  = rb + (lane >> 2);
    int c  = cb + (lane & 3) * 2;
    float2 v0 = *(const float2*)(smA + r * pitch + c * 4);
    float2 v1 = *(const float2*)(smA + (r + 8) * pitch + c * 4);
    float2 v2 = *(const float2*)(smA + r * pitch + (c + 8) * 4);
    float2 v3 = *(const float2*)(smA + (r + 8) * pitch + (c + 8) * 4);
    a[0] = pack_h2(v0.x, v0.y);
    a[1] = pack_h2(v1.x, v1.y);
    a[2] = pack_h2(v2.x, v2.y);
    a[3] = pack_h2(v3.x, v3.y);
}

// ---------------------------------------------------------------------------
// Weight prep: W[1024,128] fp32 -> 32*W fp16, transposed [n][k].
// ---------------------------------------------------------------------------
__global__ void prep_weights(const float* __restrict__ Wq,
                             const float* __restrict__ Wk,
                             const float* __restrict__ Wv)
{
    __shared__ float t[32][33];
    const int mat = blockIdx.z;
    const float* W = (mat == 0) ? Wq : (mat == 1) ? Wk : Wv;
    const int k0 = blockIdx.x * 32, n0 = blockIdx.y * 32;
    const int tx = threadIdx.x, ty = threadIdx.y;
    t[ty][tx] = W[(size_t)(k0 + ty) * Dk + n0 + tx];
    __syncthreads();
    g_Wt[(size_t)mat * 131072 + (size_t)(n0 + ty) * Ee + k0 + tx] =
        __float2half_rn(t[tx][ty] * 32.0f);
}

// ---------------------------------------------------------------------------
// Fused Q+K projection: K-chunk 64, 3-stage cp.async (halved sync count).
// 512 threads, 16 warps (4x4), warp tile 32x64.
// Stage: A 128 x 288B fp32 = 36864 | W 256 x 144B fp16 = 36864 -> 73728 B.
// 3 stages = 221184 B (fits 227KB).
// ---------------------------------------------------------------------------
#define QK_AP 288
#define QK_WP 144
#define QK_STG 73728
#define PROJQK_SMEM (3 * QK_STG)

__global__ __launch_bounds__(512, 1) void proj_qk(
    const float* __restrict__ ctx, const int* __restrict__ lens)
{
    extern __shared__ char smraw[];
    const int tid  = threadIdx.x;
    const int lane = tid & 31;
    const int wid  = tid >> 5;
    const int wm   = wid >> 2;
    const int wn   = wid & 3;
    const int m0   = blockIdx.x * 128;

    const uint32_t sbase = smem_u32(smraw);

    float acc[2][8][4];
    #pragma unroll
    for (int mt = 0; mt < 2; mt++)
        #pragma unroll
        for (int nt = 0; nt < 8; nt++)
            #pragma unroll
            for (int j = 0; j < 4; j++) acc[mt][nt][j] = 0.0f;

    const uint32_t b_row  = (uint32_t)((lane & 7) + ((lane >> 4) << 3));
    const uint32_t b_col2 = (uint32_t)((lane >> 3) & 1) * 16;

    auto copy_stage = [&](int stage, int k0) {
        const uint32_t st = sbase + stage * QK_STG;
        // A: 128 rows x 256B fp32 -> 2048 cpa16, 4/thread
        #pragma unroll
        for (int i = 0; i < 4; i++) {
            int f = tid + i * 512;
            int row = f >> 4, c = f & 15;
            cpa16(st + row * QK_AP + c * 16,
                  ctx + (size_t)(m0 + row) * Ee + k0 + c * 4);
        }
        // W: 256 rows x 128B fp16 -> 2048 cpa16, 4/thread
        #pragma unroll
        for (int i = 0; i < 4; i++) {
            int f = tid + i * 512;
            int row = f >> 3, q = f & 7;
            const __half* src = (row < 128)
                ? (g_Wt + (size_t)row * Ee)
                : (g_Wt + 131072 + (size_t)(row - 128) * Ee);
            cpa16(st + 36864 + row * QK_WP + q * 16, src + k0 + q * 8);
        }
    };

    auto do_mma = [&](int stage) {
        const char* smA = smraw + stage * QK_STG;
        const uint32_t stW = sbase + stage * QK_STG + 36864;
        #pragma unroll
        for (int ks = 0; ks < 4; ks++) {
            uint32_t af[2][4];
            #pragma unroll
            for (int mt = 0; mt < 2; mt++)
                a_frag_f32p(af[mt], smA, QK_AP, wm * 32 + mt * 16, ks * 16, lane);
            #pragma unroll
            for (int p = 0; p < 4; p++) {
                uint32_t nr = wn * 64 + p * 16 + b_row;
                uint32_t bh[4];
                LDMX4(bh, stW + nr * QK_WP + ks * 32 + b_col2);
                #pragma unroll
                for (int mt = 0; mt < 2; mt++) {
                    MMAF16(acc[mt][2*p],     af[mt], bh[0], bh[1]);
                    MMAF16(acc[mt][2*p + 1], af[mt], bh[2], bh[3]);
                }
            }
        }
    };

    copy_stage(0, 0);  CP_COMMIT;
    copy_stage(1, 64); CP_COMMIT;
    int stg = 0;
    for (int c = 0; c < 16; c++) {
        if (c < 14) { CP_WAIT(1); } else { CP_WAIT(0); }
        __syncthreads();
        if (c + 2 < 16) {
            copy_stage((stg + 2) % 3, (c + 2) * 64);
            CP_COMMIT;
        }
        do_mma(stg);
        stg = (stg + 1) % 3;
    }

    const int lenb = lens[m0 >> 11];
    const bool isQ = (wn < 2);
    __half* C = isQ ? g_Qf : g_Kf;
    const int ncc = isQ ? wn * 64 : (wn - 2) * 64;
    const float sc = isQ ? (QSCALE / 32.0f) : (1.0f / 32.0f);
    #pragma unroll
    for (int mt = 0; mt < 2; mt++) {
        int r = m0 + wm * 32 + mt * 16 + (lane >> 2);
        float mk0 = ((((r)     & 2047) < lenb) ? 1.0f : 0.0f) * sc;
        float mk1 = ((((r + 8) & 2047) < lenb) ? 1.0f : 0.0f) * sc;
        #pragma unroll
        for (int nt = 0; nt < 8; nt++) {
            int cc = ncc + nt * 8 + (lane & 3) * 2;
            *(uint32_t*)(C + (size_t)r * Dk + cc) =
                pack_h2(acc[mt][nt][0] * mk0, acc[mt][nt][1] * mk0);
            *(uint32_t*)(C + (size_t)(r + 8) * Dk + cc) =
                pack_h2(acc[mt][nt][2] * mk1, acc[mt][nt][3] * mk1);
        }
    }
}

// ---------------------------------------------------------------------------
// V projection (R12-proven): cp.async 3-stage, chunk 32, 256 threads, 2 CTA/SM.
// ---------------------------------------------------------------------------
#define APITCH 160
#define PV_STG 30720
#define PROJV_SMEM (3 * PV_STG)

__global__ __launch_bounds__(256, 2) void proj_v(
    const float* __restrict__ x, const int* __restrict__ lens)
{
    extern __shared__ char smraw[];
    const int tid  = threadIdx.x;
    const int lane = tid & 31;
    const int wid  = tid >> 5;
    const int wm   = wid >> 1;
    const int wn   = wid & 1;
    const int m0   = blockIdx.x * 128;
    const __half* W = g_Wt + 2 * 131072;

    const uint32_t sbase = smem_u32(smraw);

    float acc[2][8][4];
    #pragma unroll
    for (int mt = 0; mt < 2; mt++)
        #pragma unroll
        for (int nt = 0; nt < 8; nt++)
            #pragma unroll
            for (int j = 0; j < 4; j++) acc[mt][nt][j] = 0.0f;

    const uint32_t b_row  = (uint32_t)((lane & 7) + ((lane >> 4) << 3));
    const uint32_t b_col2 = (uint32_t)((lane >> 3) & 1) * 16;

    auto copy_stage = [&](int stage, int k0) {
        const uint32_t st = sbase + stage * PV_STG;
        #pragma unroll
        for (int i = 0; i < 4; i++) {
            int f = tid + i * 256;
            int row = f >> 3, c = f & 7;
            cpa16(st + row * APITCH + c * 16,
                  x + (size_t)(m0 + row) * Ee + k0 + c * 4);
        }
        #pragma unroll
        for (int i = 0; i < 2; i++) {
            int f = tid + i * 256;
            int row = f >> 2, q = f & 3;
            cpa16(st + 20480 + row * 80 + q * 16,
                  W + (size_t)row * Ee + k0 + q * 8);
        }
    };

    auto do_mma = [&](int stage) {
        const char* smA = smraw + stage * PV_STG;
        const uint32_t stW = sbase + stage * PV_STG + 20480;
        #pragma unroll
        for (int ks = 0; ks < 2; ks++) {
            uint32_t af[2][4];
            #pragma unroll
            for (int mt = 0; mt < 2; mt++)
                a_frag_f32p(af[mt], smA, APITCH, wm * 32 + mt * 16, ks * 16, lane);
            #pragma unroll
            for (int p = 0; p < 4; p++) {
                uint32_t nr = wn * 64 + p * 16 + b_row;
                uint32_t bh[4];
                LDMX4(bh, stW + nr * 80 + ks * 32 + b_col2);
                #pragma unroll
                for (int mt = 0; mt < 2; mt++) {
                    MMAF16(acc[mt][2*p],     af[mt], bh[0], bh[1]);
                    MMAF16(acc[mt][2*p + 1], af[mt], bh[2], bh[3]);
                }
            }
        }
    };

    copy_stage(0, 0);  CP_COMMIT;
    copy_stage(1, 32); CP_COMMIT;
    int stg = 0;
    for (int c = 0; c < 32; c++) {
        if (c < 30) { CP_WAIT(1); } else { CP_WAIT(0); }
        __syncthreads();
        if (c + 2 < 32) {
            copy_stage((stg + 2) % 3, (c + 2) * 32);
            CP_COMMIT;
        }
        do_mma(stg);
        stg = (stg + 1) % 3;
    }

    const int lenb = lens[m0 >> 11];
    const float sc = 1.0f / 32.0f;
    #pragma unroll
    for (int mt = 0; mt < 2; mt++) {
        int r = m0 + wm * 32 + mt * 16 + (lane >> 2);
        float mk0 = ((((r)     & 2047) < lenb) ? 1.0f : 0.0f) * sc;
        float mk1 = ((((r + 8) & 2047) < lenb) ? 1.0f : 0.0f) * sc;
        #pragma unroll
        for (int nt = 0; nt < 8; nt++) {
            int cc = wn * 64 + nt * 8 + (lane & 3) * 2;
            *(uint32_t*)(g_Vf + (size_t)r * Dk + cc) =
                pack_h2(acc[mt][nt][0] * mk0, acc[mt][nt][1] * mk0);
            *(uint32_t*)(g_Vf + (size_t)(r + 8) * Dk + cc) =
                pack_h2(acc[mt][nt][2] * mk1, acc[mt][nt][3] * mk1);
        }
    }
}

// ---------------------------------------------------------------------------
// Flash attention (R12-proven, 59.7us): BQ=64, BK=64, 128 threads, 2 CTAs/SM.
// Register-P, conditional rescale, diagonal-only masking, LPT.
// smem: Q 17408 | K 2x17408 | V 17408 = 69632 B.
// ---------------------------------------------------------------------------
#define AQP 272
#define SM_Qf 0
#define SM_K  17408
#define SM_V  52224
#define ATTN_SMEM 69632

__global__ __launch_bounds__(128, 2) void attn_mma(
    float* __restrict__ Out, const int* __restrict__ lens)
{
    extern __shared__ char sm[];
    const uint32_t sb = smem_u32(sm);
    const int tid  = threadIdx.x;
    const int lane = tid & 31;
    const int warp = tid >> 5;
    const int b    = blockIdx.x;
    const int q0   = (gridDim.y - 1 - blockIdx.y) * 64;
    const int len  = lens[b];

    const uint32_t a_row = lane & 15;
    const uint32_t a_col = (uint32_t)(lane >> 4) * 16;
    const uint32_t b_row = (lane & 7) + ((lane >> 4) << 3);
    const uint32_t b_col = (uint32_t)((lane >> 3) & 1) * 16;
    const uint32_t v_k   = (lane & 7) + ((lane >> 3) & 1) * 8;
    const uint32_t v_d   = (uint32_t)(lane >> 4) * 16;

    auto copy_Q = [&]() {
        #pragma unroll
        for (int i = 0; i < 8; i++) {
            int f = tid + i * 128;
            int row = f >> 4, c = f & 15;
            cpa16(sb + SM_Qf + row * AQP + c * 16,
                  g_Qf + (size_t)(b * Ll + q0 + row) * Dk + c * 8);
        }
    };
    auto copy_K = [&](int stage, int j0) {
        const uint32_t kb = sb + SM_K + stage * 17408;
        #pragma unroll
        for (int i = 0; i < 8; i++) {
            int f = tid + i * 128;
            int row = f >> 4, c = f & 15;
            cpa16(kb + row * AQP + c * 16,
                  g_Kf + (size_t)(b * Ll + j0 + row) * Dk + c * 8);
        }
    };
    auto copy_V = [&](int j0) {
        #pragma unroll
        for (int i = 0; i < 8; i++) {
            int f = tid + i * 128;
            int row = f >> 4, c = f & 15;
            cpa16(sb + SM_V + row * AQP + c * 16,
                  g_Vf + (size_t)(b * Ll + j0 + row) * Dk + c * 8);
        }
    };

    float o[16][4];
    #pragma unroll
    for (int nt = 0; nt < 16; nt++)
        #pragma unroll
        for (int j = 0; j < 4; j++) o[nt][j] = 0.0f;
    float mrow[2] = {-1e30f, -1e30f};
    float lrow[2] = {0.0f, 0.0f};

    const int kend = min(len, q0 + 64);

    copy_Q();
    copy_K(0, 0);
    CP_COMMIT;
    CP_WAIT(0);
    __syncthreads();

    int cur = 0;
    for (int j0 = 0; j0 < kend; j0 += 64) {
        copy_V(j0);
        CP_COMMIT;

        float s[8][4];
        #pragma unroll
        for (int t = 0; t < 8; t++)
            #pragma unroll
            for (int j = 0; j < 4; j++) s[t][j] = 0.0f;

        const uint32_t kbase = sb + SM_K + cur * 17408;
        #pragma unroll
        for (int ks = 0; ks < 8; ks++) {
            uint32_t qf[4];
            LDMX4(qf, sb + SM_Qf + (warp * 16 + a_row) * AQP + ks * 32 + a_col);
            #pragma unroll
            for (int p = 0; p < 4; p++) {
                uint32_t bh[4];
                LDMX4(bh, kbase + (p * 16 + b_row) * AQP + ks * 32 + b_col);
                MMAF16(s[2*p],     qf, bh[0], bh[1]);
                MMAF16(s[2*p + 1], qf, bh[2], bh[3]);
            }
        }

        bool more = (j0 + 64 < kend);
        if (more) {
            copy_K(cur ^ 1, j0 + 64);
            CP_COMMIT;
            CP_WAIT(1);
        } else {
            CP_WAIT(0);
        }
        __syncthreads();

        const bool nomask = (j0 + 64 <= q0 + warp * 16 + 1) && (j0 + 64 <= len);

        #pragma unroll
        for (int h = 0; h < 2; h++) {
            const int qi = q0 + warp * 16 + (lane >> 2) + h * 8;
            float mx = -1e30f;
            if (nomask) {
                #pragma unroll
                for (int t = 0; t < 8; t++)
                    mx = fmaxf(mx, fmaxf(s[t][2*h], s[t][2*h + 1]));
            } else {
                #pragma unroll
                for (int t = 0; t < 8; t++) {
                    int c = j0 + t * 8 + (lane & 3) * 2;
                    float v0 = (c     <= qi && c     < len) ? s[t][2*h]     : -1e30f;
                    float v1 = (c + 1 <= qi && c + 1 < len) ? s[t][2*h + 1] : -1e30f;
                    s[t][2*h] = v0; s[t][2*h + 1] = v1;
                    mx = fmaxf(mx, fmaxf(v0, v1));
                }
            }
            mx = fmaxf(mx, __shfl_xor_sync(0xffffffffu, mx, 1));
            mx = fmaxf(mx, __shfl_xor_sync(0xffffffffu, mx, 2));
            float mnew = fmaxf(mrow[h], mx);
            float lsum = 0.0f;
            #pragma unroll
            for (int t = 0; t < 8; t++) {
                float p0 = exp2f(s[t][2*h]     - mnew);
                float p1 = exp2f(s[t][2*h + 1] - mnew);
                lsum += p0 + p1;
                s[t][2*h] = __uint_as_float(pack_h2(p0, p1));
            }
            lsum += __shfl_xor_sync(0xffffffffu, lsum, 1);
            lsum += __shfl_xor_sync(0xffffffffu, lsum, 2);
            if (mnew > mrow[h]) {
                float alpha = exp2f(mrow[h] - mnew);
                lrow[h] = lrow[h] * alpha + lsum;
                mrow[h] = mnew;
                #pragma unroll
                for (int nt = 0; nt < 16; nt++) {
                    o[nt][2*h]     *= alpha;
                    o[nt][2*h + 1] *= alpha;
                }
            } else {
                lrow[h] += lsum;
            }
        }

        #pragma unroll
        for (int ks = 0; ks < 4; ks++) {
            uint32_t pa[4];
            pa[0] = __float_as_uint(s[2*ks][0]);
            pa[1] = __float_as_uint(s[2*ks][2]);
            pa[2] = __float_as_uint(s[2*ks + 1][0]);
            pa[3] = __float_as_uint(s[2*ks + 1][2]);
            #pragma unroll
            for (int dt = 0; dt < 8; dt++) {
                uint32_t bh[4];
                LDMX4T(bh, sb + SM_V + (ks * 16 + v_k) * AQP + dt * 32 + v_d);
                MMAF16(o[2*dt],     pa, bh[0], bh[1]);
                MMAF16(o[2*dt + 1], pa, bh[2], bh[3]);
            }
        }
        CP_WAIT(0);
        __syncthreads();
        cur ^= 1;
    }

    #pragma unroll
    for (int h = 0; h < 2; h++) {
        float inv = 1.0f / lrow[h];
        int row = q0 + warp * 16 + (lane >> 2) + h * 8;
        float* og = Out + ((size_t)(b * Ll + row)) * Dk;
        #pragma unroll
        for (int dt = 0; dt < 16; dt++) {
            float2 v;
            v.x = o[dt][2*h]     * inv;
            v.y = o[dt][2*h + 1] * inv;
            *(float2*)(og + dt * 8 + (lane & 3) * 2) = v;
        }
    }
}

// ---------------------------------------------------------------------------
extern "C" void kernel_launch(void* const* d_in, const int* in_sizes, int n_in,
                              void* d_out, int out_size)
{
    const float* x    = (const float*)d_in[0];
    const float* ctx  = (const float*)d_in[1];
    const int*   lens = (const int*)  d_in[2];
    const float* Wq   = (const float*)d_in[3];
    const float* Wk   = (const float*)d_in[4];
    const float* Wv   = (const float*)d_in[5];
    float* out = (float*)d_out;
    (void)in_sizes; (void)n_in; (void)out_size;

    prep_weights<<<dim3(32, 4, 3), dim3(32, 32)>>>(Wq, Wk, Wv);

    cudaFuncSetAttribute(proj_qk,
                         cudaFuncAttributeMaxDynamicSharedMemorySize, PROJQK_SMEM);
    proj_qk<<<Mtot / 128, 512, PROJQK_SMEM>>>(ctx, lens);

    cudaFuncSetAttribute(proj_v,
                         cudaFuncAttributeMaxDynamicSharedMemorySize, PROJV_SMEM);
    proj_v<<<Mtot / 128, 256, PROJV_SMEM>>>(x, lens);

    cudaFuncSetAttribute(attn_mma,
                         cudaFuncAttributeMaxDynamicSharedMemorySize, ATTN_SMEM);
    attn_mma<<<dim3(Bb, Ll / 64), 128, ATTN_SMEM>>>(out, lens);
}